// round 1
// baseline (speedup 1.0000x reference)
#include <cuda_runtime.h>

#define BATCH 2
#define SEQ 2048
#define NX 1024
#define NHEAD 16
#define HDIM 64
#define MROWS (BATCH * SEQ)   // 4096

// Scratch (allocation-free rule: __device__ globals)
__device__ float g_qkv[(size_t)MROWS * 3 * NX];   // [B*S, 3*NX]
__device__ float g_attn[(size_t)MROWS * NX];      // [B*S, NX] merged heads

// ---------------------------------------------------------------------------
// GEMM: C[M,N] = A[M,K] @ W[K,N] + bias[N]
// 128x128 block tile, BK=8, 8x8 per-thread register tile, 256 threads.
// ---------------------------------------------------------------------------
__global__ __launch_bounds__(256) void gemm_bias_kernel(
    const float* __restrict__ A, const float* __restrict__ W,
    const float* __restrict__ bias, float* __restrict__ C,
    int M, int N, int K)
{
    const int BM = 128, BN = 128, BK = 8;
    __shared__ float As[BK][BM];   // A tile, transposed
    __shared__ float Bs[BK][BN];

    const int tid  = threadIdx.x;
    const int crow = blockIdx.y;
    const int ccol = blockIdx.x;

    // global load mapping
    const int aRow = tid >> 1;           // 0..127
    const int aCol = (tid & 1) << 2;     // 0 or 4
    const int bRow = tid >> 5;           // 0..7
    const int bCol = (tid & 31) << 2;    // 0..124

    // compute mapping: 16x16 thread grid, each 8x8 outputs
    const int tr = (tid >> 4) << 3;      // row offset in tile
    const int tc = (tid & 15) << 3;      // col offset in tile

    const float* Ag = A + (size_t)(crow * BM + aRow) * K + aCol;
    const float* Wg = W + (size_t)bRow * N + (size_t)ccol * BN + bCol;

    float acc[8][8];
    #pragma unroll
    for (int i = 0; i < 8; ++i)
        #pragma unroll
        for (int j = 0; j < 8; ++j) acc[i][j] = 0.0f;

    for (int k0 = 0; k0 < K; k0 += BK) {
        float4 a4 = *(const float4*)(Ag + k0);
        As[aCol + 0][aRow] = a4.x;
        As[aCol + 1][aRow] = a4.y;
        As[aCol + 2][aRow] = a4.z;
        As[aCol + 3][aRow] = a4.w;
        *(float4*)(&Bs[bRow][bCol]) = *(const float4*)(Wg + (size_t)k0 * N);
        __syncthreads();

        #pragma unroll
        for (int k = 0; k < BK; ++k) {
            float4 a0 = *(const float4*)(&As[k][tr]);
            float4 a1 = *(const float4*)(&As[k][tr + 4]);
            float4 b0 = *(const float4*)(&Bs[k][tc]);
            float4 b1 = *(const float4*)(&Bs[k][tc + 4]);
            float rM[8] = {a0.x, a0.y, a0.z, a0.w, a1.x, a1.y, a1.z, a1.w};
            float rN[8] = {b0.x, b0.y, b0.z, b0.w, b1.x, b1.y, b1.z, b1.w};
            #pragma unroll
            for (int i = 0; i < 8; ++i)
                #pragma unroll
                for (int j = 0; j < 8; ++j)
                    acc[i][j] += rM[i] * rN[j];
        }
        __syncthreads();
    }

    // epilogue with bias
    float bw[8];
    {
        float4 bb0 = *(const float4*)(bias + ccol * BN + tc);
        float4 bb1 = *(const float4*)(bias + ccol * BN + tc + 4);
        bw[0] = bb0.x; bw[1] = bb0.y; bw[2] = bb0.z; bw[3] = bb0.w;
        bw[4] = bb1.x; bw[5] = bb1.y; bw[6] = bb1.z; bw[7] = bb1.w;
    }
    #pragma unroll
    for (int i = 0; i < 8; ++i) {
        float* cp = C + (size_t)(crow * BM + tr + i) * N + ccol * BN + tc;
        float4 o0, o1;
        o0.x = acc[i][0] + bw[0]; o0.y = acc[i][1] + bw[1];
        o0.z = acc[i][2] + bw[2]; o0.w = acc[i][3] + bw[3];
        o1.x = acc[i][4] + bw[4]; o1.y = acc[i][5] + bw[5];
        o1.z = acc[i][6] + bw[6]; o1.w = acc[i][7] + bw[7];
        *(float4*)(cp)     = o0;
        *(float4*)(cp + 4) = o1;
    }
}

// ---------------------------------------------------------------------------
// Flash attention: one block per (b*h, q-tile of 64). 256 threads = 16x16 grid,
// each thread owns a 4x4 micro-tile of scores / output. Online softmax.
// ---------------------------------------------------------------------------
#define LD 68  // smem row stride (floats): kills bank conflicts, keeps 16B align

__global__ __launch_bounds__(256) void attn_kernel(
    const float* __restrict__ qkv, float* __restrict__ outm)
{
    extern __shared__ float sm[];
    float* Qs  = sm;                 // [64][LD]
    float* Kts = sm + 64 * LD;       // K transposed: [d][kv]
    float* Vs  = sm + 2 * 64 * LD;   // [kv][d]
    float* Ps  = sm + 3 * 64 * LD;   // [q][kv]

    const int tid = threadIdx.x;
    const int tx = tid & 15;         // 0..15
    const int ty = tid >> 4;         // 0..15
    const int bh = blockIdx.y;
    const int b  = bh >> 4;
    const int h  = bh & 15;
    const int qt = blockIdx.x;       // q tile (0..31)

    const size_t rowStride = 3 * NX;
    const float* qbase = qkv + (size_t)b * SEQ * rowStride + h * HDIM;
    const float* kbase = qbase + NX;
    const float* vbase = qbase + 2 * NX;

    // ---- load & scale Q tile (64 x 64) ----
    #pragma unroll
    for (int it = 0; it < 4; ++it) {
        int idx = tid + it * 256;
        int r  = idx >> 4;
        int dc = (idx & 15) << 2;
        float4 q4 = *(const float4*)(qbase + (size_t)(qt * 64 + r) * rowStride + dc);
        float* qp = Qs + r * LD + dc;
        qp[0] = q4.x * 0.125f; qp[1] = q4.y * 0.125f;
        qp[2] = q4.z * 0.125f; qp[3] = q4.w * 0.125f;
    }

    float acc[4][4];
    #pragma unroll
    for (int i = 0; i < 4; ++i)
        #pragma unroll
        for (int j = 0; j < 4; ++j) acc[i][j] = 0.0f;
    float m_i[4], l_i[4];
    #pragma unroll
    for (int i = 0; i < 4; ++i) { m_i[i] = -1e30f; l_i[i] = 0.0f; }

    for (int kt = 0; kt <= qt; ++kt) {
        __syncthreads();   // prior iteration done reading Vs/Ps

        // ---- load K (transposed) and V tiles ----
        #pragma unroll
        for (int it = 0; it < 4; ++it) {
            int idx = tid + it * 256;
            int r  = idx >> 4;
            int dc = (idx & 15) << 2;
            float4 k4 = *(const float4*)(kbase + (size_t)(kt * 64 + r) * rowStride + dc);
            Kts[(dc + 0) * LD + r] = k4.x;
            Kts[(dc + 1) * LD + r] = k4.y;
            Kts[(dc + 2) * LD + r] = k4.z;
            Kts[(dc + 3) * LD + r] = k4.w;
            float4 v4 = *(const float4*)(vbase + (size_t)(kt * 64 + r) * rowStride + dc);
            *(float4*)(Vs + r * LD + dc) = v4;
        }
        __syncthreads();

        // ---- scores S = Qs @ Kts (each thread: 4 rows x 4 cols) ----
        float s[4][4];
        #pragma unroll
        for (int i = 0; i < 4; ++i)
            #pragma unroll
            for (int j = 0; j < 4; ++j) s[i][j] = 0.0f;

        #pragma unroll 2
        for (int k = 0; k < 64; k += 4) {
            float qr[4][4], kr[4][4];
            #pragma unroll
            for (int i = 0; i < 4; ++i) {
                float4 q4 = *(const float4*)(Qs + (ty * 4 + i) * LD + k);
                qr[i][0] = q4.x; qr[i][1] = q4.y; qr[i][2] = q4.z; qr[i][3] = q4.w;
            }
            #pragma unroll
            for (int kk = 0; kk < 4; ++kk) {
                float4 k4 = *(const float4*)(Kts + (k + kk) * LD + tx * 4);
                kr[kk][0] = k4.x; kr[kk][1] = k4.y; kr[kk][2] = k4.z; kr[kk][3] = k4.w;
            }
            #pragma unroll
            for (int i = 0; i < 4; ++i)
                #pragma unroll
                for (int kk = 0; kk < 4; ++kk)
                    #pragma unroll
                    for (int j = 0; j < 4; ++j)
                        s[i][j] += qr[i][kk] * kr[kk][j];
        }

        // ---- causal mask (diagonal tile only) ----
        if (kt == qt) {
            int qi0 = qt * 64 + ty * 4;
            int kj0 = kt * 64 + tx * 4;
            #pragma unroll
            for (int i = 0; i < 4; ++i)
                #pragma unroll
                for (int j = 0; j < 4; ++j)
                    if (kj0 + j > qi0 + i) s[i][j] = -1e30f;
        }

        // ---- online softmax ----
        #pragma unroll
        for (int i = 0; i < 4; ++i) {
            float mloc = fmaxf(fmaxf(s[i][0], s[i][1]), fmaxf(s[i][2], s[i][3]));
            #pragma unroll
            for (int off = 8; off > 0; off >>= 1)
                mloc = fmaxf(mloc, __shfl_xor_sync(0xffffffffu, mloc, off, 16));
            float mnew = fmaxf(m_i[i], mloc);
            float sc = __expf(m_i[i] - mnew);
            m_i[i] = mnew;
            float ls = 0.0f;
            #pragma unroll
            for (int j = 0; j < 4; ++j) {
                float p = __expf(s[i][j] - mnew);
                s[i][j] = p;
                ls += p;
            }
            #pragma unroll
            for (int off = 8; off > 0; off >>= 1)
                ls += __shfl_xor_sync(0xffffffffu, ls, off, 16);
            l_i[i] = l_i[i] * sc + ls;
            #pragma unroll
            for (int j = 0; j < 4; ++j) acc[i][j] *= sc;
        }

        // ---- stage P to smem ----
        #pragma unroll
        for (int i = 0; i < 4; ++i) {
            float4 p4;
            p4.x = s[i][0]; p4.y = s[i][1]; p4.z = s[i][2]; p4.w = s[i][3];
            *(float4*)(Ps + (ty * 4 + i) * LD + tx * 4) = p4;
        }
        __syncthreads();

        // ---- O += P @ V ----
        #pragma unroll 2
        for (int j = 0; j < 64; j += 4) {
            float pr[4][4], vr[4][4];
            #pragma unroll
            for (int i = 0; i < 4; ++i) {
                float4 p4 = *(const float4*)(Ps + (ty * 4 + i) * LD + j);
                pr[i][0] = p4.x; pr[i][1] = p4.y; pr[i][2] = p4.z; pr[i][3] = p4.w;
            }
            #pragma unroll
            for (int jj = 0; jj < 4; ++jj) {
                float4 v4 = *(const float4*)(Vs + (j + jj) * LD + tx * 4);
                vr[jj][0] = v4.x; vr[jj][1] = v4.y; vr[jj][2] = v4.z; vr[jj][3] = v4.w;
            }
            #pragma unroll
            for (int i = 0; i < 4; ++i)
                #pragma unroll
                for (int jj = 0; jj < 4; ++jj)
                    #pragma unroll
                    for (int c = 0; c < 4; ++c)
                        acc[i][c] += pr[i][jj] * vr[jj][c];
        }
    }

    // ---- epilogue: normalize and write merged-heads [B,S,NX] ----
    #pragma unroll
    for (int i = 0; i < 4; ++i) {
        float inv = 1.0f / l_i[i];
        float4 o;
        o.x = acc[i][0] * inv; o.y = acc[i][1] * inv;
        o.z = acc[i][2] * inv; o.w = acc[i][3] * inv;
        size_t row = (size_t)(b * SEQ + qt * 64 + ty * 4 + i);
        *(float4*)(outm + row * NX + h * HDIM + tx * 4) = o;
    }
}

// ---------------------------------------------------------------------------
extern "C" void kernel_launch(void* const* d_in, const int* in_sizes, int n_in,
                              void* d_out, int out_size)
{
    const float* x      = (const float*)d_in[0];
    const float* w_attn = (const float*)d_in[1];
    const float* b_attn = (const float*)d_in[2];
    const float* w_proj = (const float*)d_in[3];
    const float* b_proj = (const float*)d_in[4];
    float* out = (float*)d_out;

    float* qkv  = nullptr;
    float* attn = nullptr;
    cudaGetSymbolAddress((void**)&qkv,  g_qkv);
    cudaGetSymbolAddress((void**)&attn, g_attn);

    // 1) QKV = x @ w_attn + b_attn
    dim3 g1(3 * NX / 128, MROWS / 128);
    gemm_bias_kernel<<<g1, 256>>>(x, w_attn, b_attn, qkv, MROWS, 3 * NX, NX);

    // 2) attention
    size_t smem = (size_t)4 * 64 * LD * sizeof(float);  // 69632 B
    cudaFuncSetAttribute(attn_kernel,
                         cudaFuncAttributeMaxDynamicSharedMemorySize, (int)smem);
    dim3 g2(SEQ / 64, BATCH * NHEAD);
    attn_kernel<<<g2, 256, smem>>>(qkv, attn);

    // 3) out = attn @ w_proj + b_proj
    dim3 g3(NX / 128, MROWS / 128);
    gemm_bias_kernel<<<g3, 256>>>(attn, w_proj, b_proj, out, MROWS, NX, NX);
}

// round 3
// speedup vs baseline: 1.4401x; 1.4401x over previous
#include <cuda_runtime.h>
#include <cuda_bf16.h>
#include <cstdint>

#define BATCH 2
#define SEQ 2048
#define NX 1024
#define NHEAD 16
#define HDIM 64
#define MROWS (BATCH * SEQ)   // 4096
#define KDIM NX               // 1024

// ---------------------------------------------------------------------------
// Scratch (allocation-free rule: __device__ globals)
// ---------------------------------------------------------------------------
__device__ float g_qkv[(size_t)MROWS * 3 * NX];          // [B*S, 3*NX] fp32
__device__ float g_attn[(size_t)MROWS * NX];             // [B*S, NX] fp32
__device__ __nv_bfloat16 g_xhi[(size_t)MROWS * KDIM];
__device__ __nv_bfloat16 g_xlo[(size_t)MROWS * KDIM];
__device__ __nv_bfloat16 g_wah[(size_t)3 * NX * KDIM];   // w_attn^T [3NX, K]
__device__ __nv_bfloat16 g_wal[(size_t)3 * NX * KDIM];
__device__ __nv_bfloat16 g_wph[(size_t)NX * KDIM];       // w_proj^T [NX, K]
__device__ __nv_bfloat16 g_wpl[(size_t)NX * KDIM];
__device__ __nv_bfloat16 g_ahi[(size_t)MROWS * KDIM];
__device__ __nv_bfloat16 g_alo[(size_t)MROWS * KDIM];

// ---------------------------------------------------------------------------
// base-ISA tensor-core helpers (sm_80+; works on sm_100 base target)
// ---------------------------------------------------------------------------
__device__ __forceinline__ uint32_t smem_to_u32(const void* p) {
    uint32_t a;
    asm("{ .reg .u64 t; cvta.to.shared.u64 t, %1; cvt.u32.u64 %0, t; }"
        : "=r"(a) : "l"(p));
    return a;
}

__device__ __forceinline__ void cp16(uint32_t dst, const void* src) {
    asm volatile("cp.async.cg.shared.global [%0], [%1], 16;"
                 :: "r"(dst), "l"(src));
}
#define CP_COMMIT() asm volatile("cp.async.commit_group;" ::: "memory")
#define CP_WAIT1()  asm volatile("cp.async.wait_group 1;" ::: "memory")

__device__ __forceinline__ void ldsm4(uint32_t& r0, uint32_t& r1,
                                      uint32_t& r2, uint32_t& r3, uint32_t addr) {
    asm volatile("ldmatrix.sync.aligned.m8n8.x4.shared.b16 {%0,%1,%2,%3}, [%4];"
                 : "=r"(r0), "=r"(r1), "=r"(r2), "=r"(r3) : "r"(addr));
}

__device__ __forceinline__ void mma16816(float* d,
                                         uint32_t a0, uint32_t a1, uint32_t a2, uint32_t a3,
                                         uint32_t b0, uint32_t b1) {
    asm volatile(
        "mma.sync.aligned.m16n8k16.row.col.f32.bf16.bf16.f32 "
        "{%0,%1,%2,%3}, {%4,%5,%6,%7}, {%8,%9}, {%0,%1,%2,%3};"
        : "+f"(d[0]), "+f"(d[1]), "+f"(d[2]), "+f"(d[3])
        : "r"(a0), "r"(a1), "r"(a2), "r"(a3), "r"(b0), "r"(b1));
}

// ---------------------------------------------------------------------------
// Conversion kernels
// ---------------------------------------------------------------------------
__global__ void split_kernel(const float4* __restrict__ in,
                             __nv_bfloat16* __restrict__ hi,
                             __nv_bfloat16* __restrict__ lo, int n4) {
    int i = blockIdx.x * blockDim.x + threadIdx.x;
    if (i >= n4) return;
    float4 v = in[i];
    float vs[4] = {v.x, v.y, v.z, v.w};
    __nv_bfloat162 h2[2], l2[2];
    #pragma unroll
    for (int j = 0; j < 2; ++j) {
        __nv_bfloat16 h0 = __float2bfloat16(vs[2 * j]);
        __nv_bfloat16 h1 = __float2bfloat16(vs[2 * j + 1]);
        h2[j].x = h0; h2[j].y = h1;
        l2[j].x = __float2bfloat16(vs[2 * j]     - __bfloat162float(h0));
        l2[j].y = __float2bfloat16(vs[2 * j + 1] - __bfloat162float(h1));
    }
    ((__nv_bfloat162*)hi)[i * 2]     = h2[0];
    ((__nv_bfloat162*)hi)[i * 2 + 1] = h2[1];
    ((__nv_bfloat162*)lo)[i * 2]     = l2[0];
    ((__nv_bfloat162*)lo)[i * 2 + 1] = l2[1];
}

// W [K,N] fp32 -> Wt hi/lo [N,K] bf16
__global__ void transpose_split_kernel(const float* __restrict__ W,
                                       __nv_bfloat16* __restrict__ th,
                                       __nv_bfloat16* __restrict__ tl,
                                       int K, int N) {
    __shared__ float t[32][33];
    int n0 = blockIdx.x * 32, k0 = blockIdx.y * 32;
    int tx = threadIdx.x, ty = threadIdx.y;
    #pragma unroll
    for (int i = ty; i < 32; i += 8)
        t[i][tx] = W[(size_t)(k0 + i) * N + n0 + tx];
    __syncthreads();
    #pragma unroll
    for (int i = ty; i < 32; i += 8) {
        float v = t[tx][i];                    // = W[k0+tx][n0+i]
        size_t o = (size_t)(n0 + i) * K + k0 + tx;
        __nv_bfloat16 h = __float2bfloat16(v);
        th[o] = h;
        tl[o] = __float2bfloat16(v - __bfloat162float(h));
    }
}

// ---------------------------------------------------------------------------
// mma.sync GEMM: C[M,N] = (Ah+Al)[M,K] @ (Bh+Bl)^T + bias,  B stored [N,K]
// 128x128 block tile, BK=32, 8 warps (2x4), warp tile 64x32, split-3 bf16.
// 3-stage cp.async pipeline, 80B-stride smem rows (ldmatrix conflict-free).
// ---------------------------------------------------------------------------
#define GB_THREADS 256
#define BKg 32
#define NKCHUNK (KDIM / BKg)       // 32
#define ROW_STRIDE 80              // bytes per smem row (32 bf16 data + pad)
#define TILE_SM (128 * ROW_STRIDE) // 10240
#define STAGE_SM (4 * TILE_SM)     // 40960  (Ah, Al, Bh, Bl)
#define GEMM_SMEM (3 * STAGE_SM)   // 122880

__global__ __launch_bounds__(GB_THREADS, 1) void gemm_mma(
    const __nv_bfloat16* __restrict__ Ah, const __nv_bfloat16* __restrict__ Al,
    const __nv_bfloat16* __restrict__ Bh, const __nv_bfloat16* __restrict__ Bl,
    const float* __restrict__ bias, float* __restrict__ C, int N)
{
    extern __shared__ char sm[];
    const uint32_t smb = smem_to_u32(sm);
    const int tid  = threadIdx.x;
    const int wid  = tid >> 5;
    const int lane = tid & 31;
    const int wm   = wid >> 2;     // 0..1
    const int wn   = wid & 3;      // 0..3
    const int crow = blockIdx.y;
    const int ccol = blockIdx.x;

    const __nv_bfloat16* srcs[4] = {
        Ah + (size_t)(crow * 128) * KDIM,
        Al + (size_t)(crow * 128) * KDIM,
        Bh + (size_t)(ccol * 128) * KDIM,
        Bl + (size_t)(ccol * 128) * KDIM
    };

    // ---- stage loader: 4 tiles x 128 rows x 64B data (80B stride) ----
    auto load_stage = [&](int s, int k0) {
        uint32_t sb = smb + s * STAGE_SM;
        #pragma unroll
        for (int t = 0; t < 4; ++t) {
            const char* src = (const char*)(srcs[t] + k0);
            uint32_t tb = sb + t * TILE_SM;
            #pragma unroll
            for (int it = 0; it < 2; ++it) {
                int chunk = tid + it * GB_THREADS;   // 0..511
                int r  = chunk >> 2;                 // row 0..127
                int c4 = chunk & 3;                  // 16B col 0..3
                cp16(tb + r * ROW_STRIDE + c4 * 16,
                     src + (size_t)r * (KDIM * 2) + c4 * 16);
            }
        }
    };

    float acc[4][4][4];
    #pragma unroll
    for (int i = 0; i < 4; ++i)
        #pragma unroll
        for (int j = 0; j < 4; ++j)
            #pragma unroll
            for (int k = 0; k < 4; ++k) acc[i][j][k] = 0.0f;

    // prologue: stages 0, 1
    load_stage(0, 0);
    CP_COMMIT();
    load_stage(1, BKg);
    CP_COMMIT();

    for (int c = 0; c < NKCHUNK; ++c) {
        CP_WAIT1();
        __syncthreads();
        // issue next-next stage
        if (c + 2 < NKCHUNK) load_stage((c + 2) % 3, (c + 2) * BKg);
        CP_COMMIT();

        // ---- compute stage c%3 ----
        uint32_t sb   = smb + (c % 3) * STAGE_SM;
        uint32_t Ah_b = sb;
        uint32_t Al_b = sb + TILE_SM;
        uint32_t Bh_b = sb + 2 * TILE_SM;
        uint32_t Bl_b = sb + 3 * TILE_SM;

        #pragma unroll
        for (int kk = 0; kk < 2; ++kk) {
            const int kbyte = kk * 32;
            // B fragments (hi & lo) for 4 n-tiles
            uint32_t bh[4][2], bl[4][2];
            #pragma unroll
            for (int p = 0; p < 2; ++p) {
                int n0 = wn * 32 + p * 16;
                uint32_t off = (uint32_t)(n0 + ((lane >> 4) << 3) + (lane & 7)) * ROW_STRIDE
                             + ((lane >> 3) & 1) * 16 + kbyte;
                uint32_t r0, r1, r2, r3;
                ldsm4(r0, r1, r2, r3, Bh_b + off);
                bh[p * 2][0] = r0; bh[p * 2][1] = r1;
                bh[p * 2 + 1][0] = r2; bh[p * 2 + 1][1] = r3;
                ldsm4(r0, r1, r2, r3, Bl_b + off);
                bl[p * 2][0] = r0; bl[p * 2][1] = r1;
                bl[p * 2 + 1][0] = r2; bl[p * 2 + 1][1] = r3;
            }
            // A fragments per m-tile, then 3 mma products per (mt, nt)
            #pragma unroll
            for (int mt = 0; mt < 4; ++mt) {
                int m0 = wm * 64 + mt * 16;
                uint32_t aoff = (uint32_t)(m0 + (lane & 15)) * ROW_STRIDE
                              + ((lane >> 4) << 4) + kbyte;
                uint32_t ah0, ah1, ah2, ah3, al0, al1, al2, al3;
                ldsm4(ah0, ah1, ah2, ah3, Ah_b + aoff);
                ldsm4(al0, al1, al2, al3, Al_b + aoff);
                #pragma unroll
                for (int nt = 0; nt < 4; ++nt) {
                    mma16816(acc[mt][nt], ah0, ah1, ah2, ah3, bh[nt][0], bh[nt][1]);
                    mma16816(acc[mt][nt], al0, al1, al2, al3, bh[nt][0], bh[nt][1]);
                    mma16816(acc[mt][nt], ah0, ah1, ah2, ah3, bl[nt][0], bl[nt][1]);
                }
            }
        }
    }

    // ---- epilogue ----
    #pragma unroll
    for (int mt = 0; mt < 4; ++mt) {
        int r0 = crow * 128 + wm * 64 + mt * 16 + (lane >> 2);
        #pragma unroll
        for (int nt = 0; nt < 4; ++nt) {
            int c0 = ccol * 128 + wn * 32 + nt * 8 + (lane & 3) * 2;
            float b0v = bias[c0], b1v = bias[c0 + 1];
            float2 v0, v1;
            v0.x = acc[mt][nt][0] + b0v; v0.y = acc[mt][nt][1] + b1v;
            v1.x = acc[mt][nt][2] + b0v; v1.y = acc[mt][nt][3] + b1v;
            *(float2*)(C + (size_t)r0 * N + c0)       = v0;
            *(float2*)(C + (size_t)(r0 + 8) * N + c0) = v1;
        }
    }
}

// ---------------------------------------------------------------------------
// Flash attention (unchanged): fp32 SIMT, 64-row q tiles.
// ---------------------------------------------------------------------------
#define LD 68

__global__ __launch_bounds__(256) void attn_kernel(
    const float* __restrict__ qkv, float* __restrict__ outm)
{
    extern __shared__ float smf[];
    float* Qs  = smf;
    float* Kts = smf + 64 * LD;
    float* Vs  = smf + 2 * 64 * LD;
    float* Ps  = smf + 3 * 64 * LD;

    const int tid = threadIdx.x;
    const int tx = tid & 15;
    const int ty = tid >> 4;
    const int bh = blockIdx.y;
    const int b  = bh >> 4;
    const int h  = bh & 15;
    const int qt = blockIdx.x;

    const size_t rowStride = 3 * NX;
    const float* qbase = qkv + (size_t)b * SEQ * rowStride + h * HDIM;
    const float* kbase = qbase + NX;
    const float* vbase = qbase + 2 * NX;

    #pragma unroll
    for (int it = 0; it < 4; ++it) {
        int idx = tid + it * 256;
        int r  = idx >> 4;
        int dc = (idx & 15) << 2;
        float4 q4 = *(const float4*)(qbase + (size_t)(qt * 64 + r) * rowStride + dc);
        float* qp = Qs + r * LD + dc;
        qp[0] = q4.x * 0.125f; qp[1] = q4.y * 0.125f;
        qp[2] = q4.z * 0.125f; qp[3] = q4.w * 0.125f;
    }

    float acc[4][4];
    #pragma unroll
    for (int i = 0; i < 4; ++i)
        #pragma unroll
        for (int j = 0; j < 4; ++j) acc[i][j] = 0.0f;
    float m_i[4], l_i[4];
    #pragma unroll
    for (int i = 0; i < 4; ++i) { m_i[i] = -1e30f; l_i[i] = 0.0f; }

    for (int kt = 0; kt <= qt; ++kt) {
        __syncthreads();
        #pragma unroll
        for (int it = 0; it < 4; ++it) {
            int idx = tid + it * 256;
            int r  = idx >> 4;
            int dc = (idx & 15) << 2;
            float4 k4 = *(const float4*)(kbase + (size_t)(kt * 64 + r) * rowStride + dc);
            Kts[(dc + 0) * LD + r] = k4.x;
            Kts[(dc + 1) * LD + r] = k4.y;
            Kts[(dc + 2) * LD + r] = k4.z;
            Kts[(dc + 3) * LD + r] = k4.w;
            float4 v4 = *(const float4*)(vbase + (size_t)(kt * 64 + r) * rowStride + dc);
            *(float4*)(Vs + r * LD + dc) = v4;
        }
        __syncthreads();

        float s[4][4];
        #pragma unroll
        for (int i = 0; i < 4; ++i)
            #pragma unroll
            for (int j = 0; j < 4; ++j) s[i][j] = 0.0f;

        #pragma unroll 2
        for (int k = 0; k < 64; k += 4) {
            float qr[4][4], kr[4][4];
            #pragma unroll
            for (int i = 0; i < 4; ++i) {
                float4 q4 = *(const float4*)(Qs + (ty * 4 + i) * LD + k);
                qr[i][0] = q4.x; qr[i][1] = q4.y; qr[i][2] = q4.z; qr[i][3] = q4.w;
            }
            #pragma unroll
            for (int kk = 0; kk < 4; ++kk) {
                float4 k4 = *(const float4*)(Kts + (k + kk) * LD + tx * 4);
                kr[kk][0] = k4.x; kr[kk][1] = k4.y; kr[kk][2] = k4.z; kr[kk][3] = k4.w;
            }
            #pragma unroll
            for (int i = 0; i < 4; ++i)
                #pragma unroll
                for (int kk = 0; kk < 4; ++kk)
                    #pragma unroll
                    for (int j = 0; j < 4; ++j)
                        s[i][j] += qr[i][kk] * kr[kk][j];
        }

        if (kt == qt) {
            int qi0 = qt * 64 + ty * 4;
            int kj0 = kt * 64 + tx * 4;
            #pragma unroll
            for (int i = 0; i < 4; ++i)
                #pragma unroll
                for (int j = 0; j < 4; ++j)
                    if (kj0 + j > qi0 + i) s[i][j] = -1e30f;
        }

        #pragma unroll
        for (int i = 0; i < 4; ++i) {
            float mloc = fmaxf(fmaxf(s[i][0], s[i][1]), fmaxf(s[i][2], s[i][3]));
            #pragma unroll
            for (int off = 8; off > 0; off >>= 1)
                mloc = fmaxf(mloc, __shfl_xor_sync(0xffffffffu, mloc, off, 16));
            float mnew = fmaxf(m_i[i], mloc);
            float sc = __expf(m_i[i] - mnew);
            m_i[i] = mnew;
            float ls = 0.0f;
            #pragma unroll
            for (int j = 0; j < 4; ++j) {
                float p = __expf(s[i][j] - mnew);
                s[i][j] = p;
                ls += p;
            }
            #pragma unroll
            for (int off = 8; off > 0; off >>= 1)
                ls += __shfl_xor_sync(0xffffffffu, ls, off, 16);
            l_i[i] = l_i[i] * sc + ls;
            #pragma unroll
            for (int j = 0; j < 4; ++j) acc[i][j] *= sc;
        }

        #pragma unroll
        for (int i = 0; i < 4; ++i) {
            float4 p4;
            p4.x = s[i][0]; p4.y = s[i][1]; p4.z = s[i][2]; p4.w = s[i][3];
            *(float4*)(Ps + (ty * 4 + i) * LD + tx * 4) = p4;
        }
        __syncthreads();

        #pragma unroll 2
        for (int j = 0; j < 64; j += 4) {
            float pr[4][4], vr[4][4];
            #pragma unroll
            for (int i = 0; i < 4; ++i) {
                float4 p4 = *(const float4*)(Ps + (ty * 4 + i) * LD + j);
                pr[i][0] = p4.x; pr[i][1] = p4.y; pr[i][2] = p4.z; pr[i][3] = p4.w;
            }
            #pragma unroll
            for (int jj = 0; jj < 4; ++jj) {
                float4 v4 = *(const float4*)(Vs + (j + jj) * LD + tx * 4);
                vr[jj][0] = v4.x; vr[jj][1] = v4.y; vr[jj][2] = v4.z; vr[jj][3] = v4.w;
            }
            #pragma unroll
            for (int i = 0; i < 4; ++i)
                #pragma unroll
                for (int jj = 0; jj < 4; ++jj)
                    #pragma unroll
                    for (int c = 0; c < 4; ++c)
                        acc[i][c] += pr[i][jj] * vr[jj][c];
        }
    }

    #pragma unroll
    for (int i = 0; i < 4; ++i) {
        float inv = 1.0f / l_i[i];
        float4 o;
        o.x = acc[i][0] * inv; o.y = acc[i][1] * inv;
        o.z = acc[i][2] * inv; o.w = acc[i][3] * inv;
        size_t row = (size_t)(b * SEQ + qt * 64 + ty * 4 + i);
        *(float4*)(outm + row * NX + h * HDIM + tx * 4) = o;
    }
}

// ---------------------------------------------------------------------------
extern "C" void kernel_launch(void* const* d_in, const int* in_sizes, int n_in,
                              void* d_out, int out_size)
{
    const float* x      = (const float*)d_in[0];
    const float* w_attn = (const float*)d_in[1];
    const float* b_attn = (const float*)d_in[2];
    const float* w_proj = (const float*)d_in[3];
    const float* b_proj = (const float*)d_in[4];
    float* out = (float*)d_out;

    float *qkv, *attn;
    __nv_bfloat16 *xhi, *xlo, *wah, *wal, *wph, *wpl, *ahi, *alo;
    cudaGetSymbolAddress((void**)&qkv,  g_qkv);
    cudaGetSymbolAddress((void**)&attn, g_attn);
    cudaGetSymbolAddress((void**)&xhi,  g_xhi);
    cudaGetSymbolAddress((void**)&xlo,  g_xlo);
    cudaGetSymbolAddress((void**)&wah,  g_wah);
    cudaGetSymbolAddress((void**)&wal,  g_wal);
    cudaGetSymbolAddress((void**)&wph,  g_wph);
    cudaGetSymbolAddress((void**)&wpl,  g_wpl);
    cudaGetSymbolAddress((void**)&ahi,  g_ahi);
    cudaGetSymbolAddress((void**)&alo,  g_alo);

    static bool attr_done = false;
    if (!attr_done) {
        cudaFuncSetAttribute(gemm_mma,
            cudaFuncAttributeMaxDynamicSharedMemorySize, GEMM_SMEM);
        cudaFuncSetAttribute(attn_kernel,
            cudaFuncAttributeMaxDynamicSharedMemorySize,
            (int)(4 * 64 * LD * sizeof(float)));
        attr_done = true;
    }

    // 0) conversions
    {
        int n4 = MROWS * KDIM / 4;
        split_kernel<<<(n4 + 255) / 256, 256>>>((const float4*)x, xhi, xlo, n4);
    }
    transpose_split_kernel<<<dim3(3 * NX / 32, KDIM / 32), dim3(32, 8)>>>(
        w_attn, wah, wal, KDIM, 3 * NX);
    transpose_split_kernel<<<dim3(NX / 32, KDIM / 32), dim3(32, 8)>>>(
        w_proj, wph, wpl, KDIM, NX);

    // 1) QKV = x @ w_attn + b_attn   (mma.sync)
    gemm_mma<<<dim3(3 * NX / 128, MROWS / 128), GB_THREADS, GEMM_SMEM>>>(
        xhi, xlo, wah, wal, b_attn, qkv, 3 * NX);

    // 2) attention (fp32)
    size_t smem = (size_t)4 * 64 * LD * sizeof(float);
    attn_kernel<<<dim3(SEQ / 64, BATCH * NHEAD), 256, smem>>>(qkv, attn);

    // 3) split attn output, then out = attn @ w_proj + b_proj (mma.sync)
    {
        int n4 = MROWS * KDIM / 4;
        split_kernel<<<(n4 + 255) / 256, 256>>>((const float4*)attn, ahi, alo, n4);
    }
    gemm_mma<<<dim3(NX / 128, MROWS / 128), GB_THREADS, GEMM_SMEM>>>(
        ahi, alo, wph, wpl, b_proj, out, NX);
}

// round 5
// speedup vs baseline: 2.6919x; 1.8693x over previous
#include <cuda_runtime.h>
#include <cuda_bf16.h>
#include <cstdint>

#define BATCH 2
#define SEQ 2048
#define NX 1024
#define NHEAD 16
#define HDIM 64
#define MROWS (BATCH * SEQ)   // 4096
#define KDIM NX               // 1024

// ---------------------------------------------------------------------------
// Scratch (allocation-free rule: __device__ globals)
// ---------------------------------------------------------------------------
__device__ float g_qkv[(size_t)MROWS * 3 * NX];          // [B*S, 3*NX] fp32
__device__ __nv_bfloat16 g_xhi[(size_t)MROWS * KDIM];
__device__ __nv_bfloat16 g_xlo[(size_t)MROWS * KDIM];
__device__ __nv_bfloat16 g_wah[(size_t)3 * NX * KDIM];   // w_attn^T [3NX, K]
__device__ __nv_bfloat16 g_wal[(size_t)3 * NX * KDIM];
__device__ __nv_bfloat16 g_wph[(size_t)NX * KDIM];       // w_proj^T [NX, K]
__device__ __nv_bfloat16 g_wpl[(size_t)NX * KDIM];
__device__ __nv_bfloat16 g_ahi[(size_t)MROWS * KDIM];    // attn out hi
__device__ __nv_bfloat16 g_alo[(size_t)MROWS * KDIM];    // attn out lo

// ---------------------------------------------------------------------------
// base-ISA tensor-core helpers (sm_80+; works on sm_100 base target)
// ---------------------------------------------------------------------------
__device__ __forceinline__ uint32_t smem_to_u32(const void* p) {
    uint32_t a;
    asm("{ .reg .u64 t; cvta.to.shared.u64 t, %1; cvt.u32.u64 %0, t; }"
        : "=r"(a) : "l"(p));
    return a;
}

__device__ __forceinline__ void cp16(uint32_t dst, const void* src) {
    asm volatile("cp.async.cg.shared.global [%0], [%1], 16;"
                 :: "r"(dst), "l"(src));
}
#define CP_COMMIT() asm volatile("cp.async.commit_group;" ::: "memory")
#define CP_WAIT1()  asm volatile("cp.async.wait_group 1;" ::: "memory")

__device__ __forceinline__ void ldsm4(uint32_t& r0, uint32_t& r1,
                                      uint32_t& r2, uint32_t& r3, uint32_t addr) {
    asm volatile("ldmatrix.sync.aligned.m8n8.x4.shared.b16 {%0,%1,%2,%3}, [%4];"
                 : "=r"(r0), "=r"(r1), "=r"(r2), "=r"(r3) : "r"(addr));
}

__device__ __forceinline__ void ldsm4t(uint32_t& r0, uint32_t& r1,
                                       uint32_t& r2, uint32_t& r3, uint32_t addr) {
    asm volatile("ldmatrix.sync.aligned.m8n8.x4.trans.shared.b16 {%0,%1,%2,%3}, [%4];"
                 : "=r"(r0), "=r"(r1), "=r"(r2), "=r"(r3) : "r"(addr));
}

__device__ __forceinline__ void mma16816(float* d,
                                         uint32_t a0, uint32_t a1, uint32_t a2, uint32_t a3,
                                         uint32_t b0, uint32_t b1) {
    asm volatile(
        "mma.sync.aligned.m16n8k16.row.col.f32.bf16.bf16.f32 "
        "{%0,%1,%2,%3}, {%4,%5,%6,%7}, {%8,%9}, {%0,%1,%2,%3};"
        : "+f"(d[0]), "+f"(d[1]), "+f"(d[2]), "+f"(d[3])
        : "r"(a0), "r"(a1), "r"(a2), "r"(a3), "r"(b0), "r"(b1));
}

__device__ __forceinline__ uint32_t packbf(float a, float b) {
    __nv_bfloat162 t;
    t.x = __float2bfloat16(a);
    t.y = __float2bfloat16(b);
    return *(uint32_t*)&t;
}

// split one float4 into packed hi (2x u32) and lo (2x u32)
__device__ __forceinline__ void split4(float4 v, uint32_t* hi2, uint32_t* lo2) {
    __nv_bfloat16 hx = __float2bfloat16(v.x), hy = __float2bfloat16(v.y);
    __nv_bfloat16 hz = __float2bfloat16(v.z), hw = __float2bfloat16(v.w);
    __nv_bfloat162 h01; h01.x = hx; h01.y = hy;
    __nv_bfloat162 h23; h23.x = hz; h23.y = hw;
    hi2[0] = *(uint32_t*)&h01;
    hi2[1] = *(uint32_t*)&h23;
    lo2[0] = packbf(v.x - __bfloat162float(hx), v.y - __bfloat162float(hy));
    lo2[1] = packbf(v.z - __bfloat162float(hz), v.w - __bfloat162float(hw));
}

// ---------------------------------------------------------------------------
// Conversion kernels
// ---------------------------------------------------------------------------
__global__ void split_kernel(const float4* __restrict__ in,
                             __nv_bfloat16* __restrict__ hi,
                             __nv_bfloat16* __restrict__ lo, int n4) {
    int i = blockIdx.x * blockDim.x + threadIdx.x;
    if (i >= n4) return;
    uint32_t h2[2], l2[2];
    split4(in[i], h2, l2);
    ((uint32_t*)hi)[i * 2]     = h2[0];
    ((uint32_t*)hi)[i * 2 + 1] = h2[1];
    ((uint32_t*)lo)[i * 2]     = l2[0];
    ((uint32_t*)lo)[i * 2 + 1] = l2[1];
}

// W [K,N] fp32 -> Wt hi/lo [N,K] bf16
__global__ void transpose_split_kernel(const float* __restrict__ W,
                                       __nv_bfloat16* __restrict__ th,
                                       __nv_bfloat16* __restrict__ tl,
                                       int K, int N) {
    __shared__ float t[32][33];
    int n0 = blockIdx.x * 32, k0 = blockIdx.y * 32;
    int tx = threadIdx.x, ty = threadIdx.y;
    #pragma unroll
    for (int i = ty; i < 32; i += 8)
        t[i][tx] = W[(size_t)(k0 + i) * N + n0 + tx];
    __syncthreads();
    #pragma unroll
    for (int i = ty; i < 32; i += 8) {
        float v = t[tx][i];
        size_t o = (size_t)(n0 + i) * K + k0 + tx;
        __nv_bfloat16 h = __float2bfloat16(v);
        th[o] = h;
        tl[o] = __float2bfloat16(v - __bfloat162float(h));
    }
}

// ---------------------------------------------------------------------------
// mma.sync GEMM (unchanged from round 3)
// ---------------------------------------------------------------------------
#define GB_THREADS 256
#define BKg 32
#define NKCHUNK (KDIM / BKg)
#define ROW_STRIDE 80
#define TILE_SM (128 * ROW_STRIDE)
#define STAGE_SM (4 * TILE_SM)
#define GEMM_SMEM (3 * STAGE_SM)

__global__ __launch_bounds__(GB_THREADS, 1) void gemm_mma(
    const __nv_bfloat16* __restrict__ Ah, const __nv_bfloat16* __restrict__ Al,
    const __nv_bfloat16* __restrict__ Bh, const __nv_bfloat16* __restrict__ Bl,
    const float* __restrict__ bias, float* __restrict__ C, int N)
{
    extern __shared__ char sm[];
    const uint32_t smb = smem_to_u32(sm);
    const int tid  = threadIdx.x;
    const int wid  = tid >> 5;
    const int lane = tid & 31;
    const int wm   = wid >> 2;
    const int wn   = wid & 3;
    const int crow = blockIdx.y;
    const int ccol = blockIdx.x;

    const __nv_bfloat16* srcs[4] = {
        Ah + (size_t)(crow * 128) * KDIM,
        Al + (size_t)(crow * 128) * KDIM,
        Bh + (size_t)(ccol * 128) * KDIM,
        Bl + (size_t)(ccol * 128) * KDIM
    };

    auto load_stage = [&](int s, int k0) {
        uint32_t sb = smb + s * STAGE_SM;
        #pragma unroll
        for (int t = 0; t < 4; ++t) {
            const char* src = (const char*)(srcs[t] + k0);
            uint32_t tb = sb + t * TILE_SM;
            #pragma unroll
            for (int it = 0; it < 2; ++it) {
                int chunk = tid + it * GB_THREADS;
                int r  = chunk >> 2;
                int c4 = chunk & 3;
                cp16(tb + r * ROW_STRIDE + c4 * 16,
                     src + (size_t)r * (KDIM * 2) + c4 * 16);
            }
        }
    };

    float acc[4][4][4];
    #pragma unroll
    for (int i = 0; i < 4; ++i)
        #pragma unroll
        for (int j = 0; j < 4; ++j)
            #pragma unroll
            for (int k = 0; k < 4; ++k) acc[i][j][k] = 0.0f;

    load_stage(0, 0);
    CP_COMMIT();
    load_stage(1, BKg);
    CP_COMMIT();

    for (int c = 0; c < NKCHUNK; ++c) {
        CP_WAIT1();
        __syncthreads();
        if (c + 2 < NKCHUNK) load_stage((c + 2) % 3, (c + 2) * BKg);
        CP_COMMIT();

        uint32_t sb   = smb + (c % 3) * STAGE_SM;
        uint32_t Ah_b = sb;
        uint32_t Al_b = sb + TILE_SM;
        uint32_t Bh_b = sb + 2 * TILE_SM;
        uint32_t Bl_b = sb + 3 * TILE_SM;

        #pragma unroll
        for (int kk = 0; kk < 2; ++kk) {
            const int kbyte = kk * 32;
            uint32_t bh[4][2], bl[4][2];
            #pragma unroll
            for (int p = 0; p < 2; ++p) {
                int n0 = wn * 32 + p * 16;
                uint32_t off = (uint32_t)(n0 + ((lane >> 4) << 3) + (lane & 7)) * ROW_STRIDE
                             + ((lane >> 3) & 1) * 16 + kbyte;
                uint32_t r0, r1, r2, r3;
                ldsm4(r0, r1, r2, r3, Bh_b + off);
                bh[p * 2][0] = r0; bh[p * 2][1] = r1;
                bh[p * 2 + 1][0] = r2; bh[p * 2 + 1][1] = r3;
                ldsm4(r0, r1, r2, r3, Bl_b + off);
                bl[p * 2][0] = r0; bl[p * 2][1] = r1;
                bl[p * 2 + 1][0] = r2; bl[p * 2 + 1][1] = r3;
            }
            #pragma unroll
            for (int mt = 0; mt < 4; ++mt) {
                int m0 = wm * 64 + mt * 16;
                uint32_t aoff = (uint32_t)(m0 + (lane & 15)) * ROW_STRIDE
                              + ((lane >> 4) << 4) + kbyte;
                uint32_t ah0, ah1, ah2, ah3, al0, al1, al2, al3;
                ldsm4(ah0, ah1, ah2, ah3, Ah_b + aoff);
                ldsm4(al0, al1, al2, al3, Al_b + aoff);
                #pragma unroll
                for (int nt = 0; nt < 4; ++nt) {
                    mma16816(acc[mt][nt], ah0, ah1, ah2, ah3, bh[nt][0], bh[nt][1]);
                    mma16816(acc[mt][nt], al0, al1, al2, al3, bh[nt][0], bh[nt][1]);
                    mma16816(acc[mt][nt], ah0, ah1, ah2, ah3, bl[nt][0], bl[nt][1]);
                }
            }
        }
    }

    #pragma unroll
    for (int mt = 0; mt < 4; ++mt) {
        int r0 = crow * 128 + wm * 64 + mt * 16 + (lane >> 2);
        #pragma unroll
        for (int nt = 0; nt < 4; ++nt) {
            int c0 = ccol * 128 + wn * 32 + nt * 8 + (lane & 3) * 2;
            float b0v = bias[c0], b1v = bias[c0 + 1];
            float2 v0, v1;
            v0.x = acc[mt][nt][0] + b0v; v0.y = acc[mt][nt][1] + b1v;
            v1.x = acc[mt][nt][2] + b0v; v1.y = acc[mt][nt][3] + b1v;
            *(float2*)(C + (size_t)r0 * N + c0)       = v0;
            *(float2*)(C + (size_t)(r0 + 8) * N + c0) = v1;
        }
    }
}

// ---------------------------------------------------------------------------
// Flash attention with mma.sync, split-3 bf16 for QK^T and P·V.
// Block: 128 q rows x one (b,h). 8 warps x 16 q rows. kv tiles of 128.
// Epilogue writes bf16 hi/lo directly (proj GEMM input).
// ---------------------------------------------------------------------------
#define AROW 144                   // smem row stride bytes (64 bf16 + pad)
#define ATILE (128 * AROW)         // 18432
#define ASMEM (6 * ATILE)          // 110592: Qh Ql Kh Kl Vh Vl

__global__ __launch_bounds__(256, 1) void attn_mma(
    const float* __restrict__ qkv,
    __nv_bfloat16* __restrict__ ohi, __nv_bfloat16* __restrict__ olo)
{
    extern __shared__ char sm[];
    const uint32_t smb = smem_to_u32(sm);
    const uint32_t Qh_b = smb;
    const uint32_t Ql_b = smb + ATILE;
    const uint32_t Kh_b = smb + 2 * ATILE;
    const uint32_t Kl_b = smb + 3 * ATILE;
    const uint32_t Vh_b = smb + 4 * ATILE;
    const uint32_t Vl_b = smb + 5 * ATILE;

    const int tid  = threadIdx.x;
    const int wid  = tid >> 5;
    const int lane = tid & 31;
    const int bh = blockIdx.x;
    const int b  = bh >> 4;
    const int h  = bh & 15;
    const int qt = (int)(gridDim.y - 1) - (int)blockIdx.y;  // heavy blocks first

    const size_t RS = 3 * NX;
    const float* qsrc = qkv + (size_t)b * SEQ * RS + h * HDIM;
    const float* ksrc = qsrc + NX;
    const float* vsrc = qsrc + 2 * NX;

    // ---- load + scale + split Q tile into smem ----
    {
        const float* src = qsrc + (size_t)(qt * 128) * RS;
        #pragma unroll
        for (int it = 0; it < 8; ++it) {
            int chunk = tid + it * 256;
            int r = chunk >> 4, c4 = chunk & 15;
            float4 v = *(const float4*)(src + (size_t)r * RS + c4 * 4);
            v.x *= 0.125f; v.y *= 0.125f; v.z *= 0.125f; v.w *= 0.125f;
            uint32_t h2[2], l2[2];
            split4(v, h2, l2);
            uint32_t off = (uint32_t)r * AROW + c4 * 8;
            ((uint32_t*)(sm + off))[0] = h2[0];
            ((uint32_t*)(sm + off))[1] = h2[1];
            ((uint32_t*)(sm + ATILE + off))[0] = l2[0];
            ((uint32_t*)(sm + ATILE + off))[1] = l2[1];
        }
    }
    __syncthreads();

    // ---- Q fragments (loop-invariant): [kstep 0..3][4 regs], hi & lo ----
    uint32_t qh[4][4], ql[4][4];
    #pragma unroll
    for (int ks = 0; ks < 4; ++ks) {
        uint32_t aoff = (uint32_t)(wid * 16 + (lane & 15)) * AROW
                      + ((lane >> 4) << 4) + ks * 32;
        ldsm4(qh[ks][0], qh[ks][1], qh[ks][2], qh[ks][3], Qh_b + aoff);
        ldsm4(ql[ks][0], ql[ks][1], ql[ks][2], ql[ks][3], Ql_b + aoff);
    }

    float o[8][4];
    #pragma unroll
    for (int i = 0; i < 8; ++i)
        #pragma unroll
        for (int j = 0; j < 4; ++j) o[i][j] = 0.0f;
    float m0 = -1e30f, m1 = -1e30f, l0 = 0.0f, l1 = 0.0f;

    for (int kt = 0; kt <= qt; ++kt) {
        __syncthreads();   // previous tile's mma reads done

        // ---- load + split K, V tiles ----
        #pragma unroll
        for (int tns = 0; tns < 2; ++tns) {
            const float* src = (tns == 0 ? ksrc : vsrc) + (size_t)(kt * 128) * RS;
            uint32_t hb = (tns == 0 ? Kh_b : Vh_b) - smb;
            uint32_t lb = (tns == 0 ? Kl_b : Vl_b) - smb;
            #pragma unroll
            for (int it = 0; it < 8; ++it) {
                int chunk = tid + it * 256;
                int r = chunk >> 4, c4 = chunk & 15;
                float4 v = *(const float4*)(src + (size_t)r * RS + c4 * 4);
                uint32_t h2[2], l2[2];
                split4(v, h2, l2);
                uint32_t off = (uint32_t)r * AROW + c4 * 8;
                ((uint32_t*)(sm + hb + off))[0] = h2[0];
                ((uint32_t*)(sm + hb + off))[1] = h2[1];
                ((uint32_t*)(sm + lb + off))[0] = l2[0];
                ((uint32_t*)(sm + lb + off))[1] = l2[1];
            }
        }
        __syncthreads();

        // ---- scores S = Q K^T : 16 n-tiles of 8 kv ----
        float s[16][4];
        #pragma unroll
        for (int t = 0; t < 16; ++t)
            #pragma unroll
            for (int j = 0; j < 4; ++j) s[t][j] = 0.0f;

        #pragma unroll
        for (int ks = 0; ks < 4; ++ks) {
            #pragma unroll
            for (int nt2 = 0; nt2 < 8; ++nt2) {
                uint32_t off = (uint32_t)(nt2 * 16 + ((lane >> 4) << 3) + (lane & 7)) * AROW
                             + (((lane >> 3) & 1) << 4) + ks * 32;
                uint32_t h0, h1, h2, h3, lo0, lo1, lo2, lo3;
                ldsm4(h0, h1, h2, h3, Kh_b + off);
                ldsm4(lo0, lo1, lo2, lo3, Kl_b + off);
                mma16816(s[2 * nt2],     qh[ks][0], qh[ks][1], qh[ks][2], qh[ks][3], h0, h1);
                mma16816(s[2 * nt2],     ql[ks][0], ql[ks][1], ql[ks][2], ql[ks][3], h0, h1);
                mma16816(s[2 * nt2],     qh[ks][0], qh[ks][1], qh[ks][2], qh[ks][3], lo0, lo1);
                mma16816(s[2 * nt2 + 1], qh[ks][0], qh[ks][1], qh[ks][2], qh[ks][3], h2, h3);
                mma16816(s[2 * nt2 + 1], ql[ks][0], ql[ks][1], ql[ks][2], ql[ks][3], h2, h3);
                mma16816(s[2 * nt2 + 1], qh[ks][0], qh[ks][1], qh[ks][2], qh[ks][3], lo2, lo3);
            }
        }

        // ---- causal mask on diagonal block ----
        if (kt == qt) {
            int r0 = wid * 16 + (lane >> 2);
            int r1 = r0 + 8;
            int cb = (lane & 3) * 2;
            #pragma unroll
            for (int t = 0; t < 16; ++t) {
                int c = 8 * t + cb;
                if (c     > r0) s[t][0] = -1e30f;
                if (c + 1 > r0) s[t][1] = -1e30f;
                if (c     > r1) s[t][2] = -1e30f;
                if (c + 1 > r1) s[t][3] = -1e30f;
            }
        }

        // ---- online softmax ----
        {
            float mx0 = -1e30f, mx1 = -1e30f;
            #pragma unroll
            for (int t = 0; t < 16; ++t) {
                mx0 = fmaxf(mx0, fmaxf(s[t][0], s[t][1]));
                mx1 = fmaxf(mx1, fmaxf(s[t][2], s[t][3]));
            }
            #pragma unroll
            for (int off = 1; off <= 2; off <<= 1) {
                mx0 = fmaxf(mx0, __shfl_xor_sync(0xffffffffu, mx0, off));
                mx1 = fmaxf(mx1, __shfl_xor_sync(0xffffffffu, mx1, off));
            }
            float mn0 = fmaxf(m0, mx0), mn1 = fmaxf(m1, mx1);
            float sc0 = __expf(m0 - mn0), sc1 = __expf(m1 - mn1);
            m0 = mn0; m1 = mn1;
            float ls0 = 0.0f, ls1 = 0.0f;
            #pragma unroll
            for (int t = 0; t < 16; ++t) {
                s[t][0] = __expf(s[t][0] - mn0);
                s[t][1] = __expf(s[t][1] - mn0);
                s[t][2] = __expf(s[t][2] - mn1);
                s[t][3] = __expf(s[t][3] - mn1);
                ls0 += s[t][0] + s[t][1];
                ls1 += s[t][2] + s[t][3];
            }
            #pragma unroll
            for (int off = 1; off <= 2; off <<= 1) {
                ls0 += __shfl_xor_sync(0xffffffffu, ls0, off);
                ls1 += __shfl_xor_sync(0xffffffffu, ls1, off);
            }
            l0 = l0 * sc0 + ls0;
            l1 = l1 * sc1 + ls1;
            #pragma unroll
            for (int i = 0; i < 8; ++i) {
                o[i][0] *= sc0; o[i][1] *= sc0;
                o[i][2] *= sc1; o[i][3] *= sc1;
            }
        }

        // ---- O += P V : 8 k-steps of 16 kv, 4 d n-tile pairs ----
        #pragma unroll
        for (int ks8 = 0; ks8 < 8; ++ks8) {
            // P fragments (hi/lo) straight from score registers
            float p00 = s[2 * ks8][0],     p01 = s[2 * ks8][1];
            float p10 = s[2 * ks8][2],     p11 = s[2 * ks8][3];
            float p20 = s[2 * ks8 + 1][0], p21 = s[2 * ks8 + 1][1];
            float p30 = s[2 * ks8 + 1][2], p31 = s[2 * ks8 + 1][3];
            uint32_t ah0 = packbf(p00, p01), ah1 = packbf(p10, p11);
            uint32_t ah2 = packbf(p20, p21), ah3 = packbf(p30, p31);
            __nv_bfloat162 t0 = *(__nv_bfloat162*)&ah0;
            __nv_bfloat162 t1 = *(__nv_bfloat162*)&ah1;
            __nv_bfloat162 t2 = *(__nv_bfloat162*)&ah2;
            __nv_bfloat162 t3 = *(__nv_bfloat162*)&ah3;
            uint32_t al0 = packbf(p00 - __bfloat162float(t0.x), p01 - __bfloat162float(t0.y));
            uint32_t al1 = packbf(p10 - __bfloat162float(t1.x), p11 - __bfloat162float(t1.y));
            uint32_t al2 = packbf(p20 - __bfloat162float(t2.x), p21 - __bfloat162float(t2.y));
            uint32_t al3 = packbf(p30 - __bfloat162float(t3.x), p31 - __bfloat162float(t3.y));

            #pragma unroll
            for (int nt2 = 0; nt2 < 4; ++nt2) {
                uint32_t off = (uint32_t)(ks8 * 16 + (lane & 15)) * AROW
                             + nt2 * 32 + ((lane >> 4) << 4);
                uint32_t vh0, vh1, vh2, vh3, vl0, vl1, vl2, vl3;
                ldsm4t(vh0, vh1, vh2, vh3, Vh_b + off);
                ldsm4t(vl0, vl1, vl2, vl3, Vl_b + off);
                mma16816(o[2 * nt2],     ah0, ah1, ah2, ah3, vh0, vh1);
                mma16816(o[2 * nt2],     al0, al1, al2, al3, vh0, vh1);
                mma16816(o[2 * nt2],     ah0, ah1, ah2, ah3, vl0, vl1);
                mma16816(o[2 * nt2 + 1], ah0, ah1, ah2, ah3, vh2, vh3);
                mma16816(o[2 * nt2 + 1], al0, al1, al2, al3, vh2, vh3);
                mma16816(o[2 * nt2 + 1], ah0, ah1, ah2, ah3, vl2, vl3);
            }
        }
    }

    // ---- epilogue: normalize, split to bf16 hi/lo, store ----
    {
        float inv0 = 1.0f / l0, inv1 = 1.0f / l1;
        int r0 = qt * 128 + wid * 16 + (lane >> 2);
        size_t row0 = (size_t)(b * SEQ + r0);
        size_t row1 = row0 + 8;
        int colb = h * HDIM + (lane & 3) * 2;
        #pragma unroll
        for (int nt = 0; nt < 8; ++nt) {
            float a0 = o[nt][0] * inv0, a1 = o[nt][1] * inv0;
            float b0 = o[nt][2] * inv1, b1 = o[nt][3] * inv1;
            uint32_t h0p = packbf(a0, a1);
            uint32_t h1p = packbf(b0, b1);
            __nv_bfloat162 t0 = *(__nv_bfloat162*)&h0p;
            __nv_bfloat162 t1 = *(__nv_bfloat162*)&h1p;
            uint32_t l0p = packbf(a0 - __bfloat162float(t0.x), a1 - __bfloat162float(t0.y));
            uint32_t l1p = packbf(b0 - __bfloat162float(t1.x), b1 - __bfloat162float(t1.y));
            int c = colb + nt * 8;
            *(uint32_t*)(ohi + row0 * NX + c) = h0p;
            *(uint32_t*)(ohi + row1 * NX + c) = h1p;
            *(uint32_t*)(olo + row0 * NX + c) = l0p;
            *(uint32_t*)(olo + row1 * NX + c) = l1p;
        }
    }
}

// ---------------------------------------------------------------------------
extern "C" void kernel_launch(void* const* d_in, const int* in_sizes, int n_in,
                              void* d_out, int out_size)
{
    const float* x      = (const float*)d_in[0];
    const float* w_attn = (const float*)d_in[1];
    const float* b_attn = (const float*)d_in[2];
    const float* w_proj = (const float*)d_in[3];
    const float* b_proj = (const float*)d_in[4];
    float* out = (float*)d_out;

    float *qkv;
    __nv_bfloat16 *xhi, *xlo, *wah, *wal, *wph, *wpl, *ahi, *alo;
    cudaGetSymbolAddress((void**)&qkv,  g_qkv);
    cudaGetSymbolAddress((void**)&xhi,  g_xhi);
    cudaGetSymbolAddress((void**)&xlo,  g_xlo);
    cudaGetSymbolAddress((void**)&wah,  g_wah);
    cudaGetSymbolAddress((void**)&wal,  g_wal);
    cudaGetSymbolAddress((void**)&wph,  g_wph);
    cudaGetSymbolAddress((void**)&wpl,  g_wpl);
    cudaGetSymbolAddress((void**)&ahi,  g_ahi);
    cudaGetSymbolAddress((void**)&alo,  g_alo);

    static bool attr_done = false;
    if (!attr_done) {
        cudaFuncSetAttribute(gemm_mma,
            cudaFuncAttributeMaxDynamicSharedMemorySize, GEMM_SMEM);
        cudaFuncSetAttribute(attn_mma,
            cudaFuncAttributeMaxDynamicSharedMemorySize, ASMEM);
        attr_done = true;
    }

    // 0) conversions
    {
        int n4 = MROWS * KDIM / 4;
        split_kernel<<<(n4 + 255) / 256, 256>>>((const float4*)x, xhi, xlo, n4);
    }
    transpose_split_kernel<<<dim3(3 * NX / 32, KDIM / 32), dim3(32, 8)>>>(
        w_attn, wah, wal, KDIM, 3 * NX);
    transpose_split_kernel<<<dim3(NX / 32, KDIM / 32), dim3(32, 8)>>>(
        w_proj, wph, wpl, KDIM, NX);

    // 1) QKV = x @ w_attn + b_attn   (mma.sync)
    gemm_mma<<<dim3(3 * NX / 128, MROWS / 128), GB_THREADS, GEMM_SMEM>>>(
        xhi, xlo, wah, wal, b_attn, qkv, 3 * NX);

    // 2) attention (mma.sync flash) -> writes bf16 hi/lo for proj
    attn_mma<<<dim3(BATCH * NHEAD, SEQ / 128), 256, ASMEM>>>(qkv, ahi, alo);

    // 3) out = attn @ w_proj + b_proj (mma.sync)
    gemm_mma<<<dim3(NX / 128, MROWS / 128), GB_THREADS, GEMM_SMEM>>>(
        ahi, alo, wph, wpl, b_proj, out, NX);
}